// round 1
// baseline (speedup 1.0000x reference)
#include <cuda_runtime.h>
#include <math.h>

#define N 4096
#define KDIM 1024
#define NN ((size_t)N*(size_t)N)
#define OT_EPS 1e-6f
#define RC (1.0f/4096.0f)

// ---------------- device scratch (static: allocation-guard safe) ----------------
__device__ float g_P0[16777216];                 // 64 MB: exp(M - rowmax)
__device__ float g_u[N], g_v[N], g_z[N], g_w[N], g_s[N], g_sinv[N];
__device__ float g_rowmax[N], g_rinvA[N], g_rinvB[N];
__device__ float g_sum, g_sumsq, g_mean, g_istd, g_psum, g_pdiag;
__device__ int   g_done;

// ---------------- init: reset all per-launch state (graph replays!) -------------
__global__ void k_init() {
    int t = threadIdx.x;
    if (t == 0) { g_sum = 0.f; g_sumsq = 0.f; g_psum = 0.f; g_pdiag = 0.f; g_done = 0; }
    for (int j = t; j < N; j += 256) g_v[j] = 1.0f;
}

// ---------------- inverse row norms of ft (rows 0..N-1) and fs (N..2N-1) --------
__global__ void k_rownorms(const float* __restrict__ ft, const float* __restrict__ fs) {
    int row = blockIdx.x;
    const float* src = (row < N) ? (ft + (size_t)row * KDIM)
                                 : (fs + (size_t)(row - N) * KDIM);
    int t = threadIdx.x;                 // 256 threads, 256 float4 = 1024 floats
    float4 v = ((const float4*)src)[t];
    float ss = v.x*v.x + v.y*v.y + v.z*v.z + v.w*v.w;
    __shared__ float red[256];
    red[t] = ss; __syncthreads();
    for (int o = 128; o; o >>= 1) { if (t < o) red[t] += red[t + o]; __syncthreads(); }
    if (t == 0) {
        float inv = 1.0f / fmaxf(sqrtf(red[0]), 1e-12f);
        if (row < N) g_rinvA[row] = inv; else g_rinvB[row - N] = inv;
    }
}

// ---------------- SGEMM: Mraw[i][j] = rinvA[i]*rinvB[j]*dot(ft_i, fs_j) ---------
// 128x128 tile, K-step 16, 256 threads, 8x8 per thread.
__global__ void __launch_bounds__(256, 2)
k_gemm(const float* __restrict__ A, const float* __restrict__ B, float* __restrict__ Mout) {
    __shared__ float As[16][132];
    __shared__ float Bs[16][132];
    int tid = threadIdx.x;
    int tx = tid & 15, ty = tid >> 4;
    int bx = blockIdx.x, by = blockIdx.y;
    const float* Ab = A + (size_t)by * 128 * KDIM;
    const float* Bb = B + (size_t)bx * 128 * KDIM;

    float acc[8][8];
#pragma unroll
    for (int m = 0; m < 8; m++)
#pragma unroll
        for (int n = 0; n < 8; n++) acc[m][n] = 0.f;

    for (int k0 = 0; k0 < KDIM; k0 += 16) {
#pragma unroll
        for (int l = 0; l < 2; l++) {
            int idx = tid + l * 256;          // 0..511
            int row = idx >> 2;               // 0..127
            int kq  = (idx & 3) << 2;         // 0,4,8,12
            float4 av = *(const float4*)(Ab + (size_t)row * KDIM + k0 + kq);
            As[kq+0][row] = av.x; As[kq+1][row] = av.y;
            As[kq+2][row] = av.z; As[kq+3][row] = av.w;
            float4 bv = *(const float4*)(Bb + (size_t)row * KDIM + k0 + kq);
            Bs[kq+0][row] = bv.x; Bs[kq+1][row] = bv.y;
            Bs[kq+2][row] = bv.z; Bs[kq+3][row] = bv.w;
        }
        __syncthreads();
#pragma unroll
        for (int k = 0; k < 16; k++) {
            float4 a0 = *(const float4*)&As[k][ty * 4];
            float4 a1 = *(const float4*)&As[k][64 + ty * 4];
            float4 b0 = *(const float4*)&Bs[k][tx * 4];
            float4 b1 = *(const float4*)&Bs[k][64 + tx * 4];
            float a[8] = {a0.x,a0.y,a0.z,a0.w,a1.x,a1.y,a1.z,a1.w};
            float b[8] = {b0.x,b0.y,b0.z,b0.w,b1.x,b1.y,b1.z,b1.w};
#pragma unroll
            for (int m = 0; m < 8; m++)
#pragma unroll
                for (int n = 0; n < 8; n++) acc[m][n] += a[m] * b[n];
        }
        __syncthreads();
    }

    int ibase = by * 128, jbase = bx * 128;
    float rb[8];
#pragma unroll
    for (int n = 0; n < 8; n++) {
        int j = jbase + (n < 4 ? tx * 4 + n : 64 + tx * 4 + (n - 4));
        rb[n] = g_rinvB[j];
    }
#pragma unroll
    for (int m = 0; m < 8; m++) {
        int i = ibase + (m < 4 ? ty * 4 + m : 64 + ty * 4 + (m - 4));
        float ra = g_rinvA[i];
#pragma unroll
        for (int n = 0; n < 8; n++) {
            int j = jbase + (n < 4 ? tx * 4 + n : 64 + tx * 4 + (n - 4));
            Mout[(size_t)i * N + j] = acc[m][n] * ra * rb[n];
        }
    }
}

// ---------------- per-row stats of raw M: sum, sumsq (global), rowmax -----------
__global__ void k_stats(const float* __restrict__ Mraw) {
    int i = blockIdx.x, t = threadIdx.x;
    const float* row = Mraw + (size_t)i * N;
    float s = 0.f, s2 = 0.f, mx = -1e30f;
#pragma unroll
    for (int k = 0; k < 16; k++) {
        float v = row[t + 256 * k];
        s += v; s2 += v * v; mx = fmaxf(mx, v);
    }
    __shared__ float rs[256], rq[256], rm[256];
    rs[t] = s; rq[t] = s2; rm[t] = mx; __syncthreads();
    for (int o = 128; o; o >>= 1) {
        if (t < o) { rs[t] += rs[t+o]; rq[t] += rq[t+o]; rm[t] = fmaxf(rm[t], rm[t+o]); }
        __syncthreads();
    }
    if (t == 0) {
        atomicAdd(&g_sum, rs[0]);
        atomicAdd(&g_sumsq, rq[0]);
        g_rowmax[i] = rm[0];
    }
}

__global__ void k_stats2() {
    double s = (double)g_sum, s2 = (double)g_sumsq;
    double n = (double)NN;
    double mean = s / n;
    double var = (s2 - n * mean * mean) / (n - 1.0);   // ddof=1
    g_mean = (float)mean;
    g_istd = (float)(1.0 / sqrt(var));
}

// ---------------- standardize M in place, build P0 = exp((M'-rowmax')*istd) -----
__global__ void k_makeP0(float* __restrict__ Mio) {
    int i = blockIdx.x, t = threadIdx.x;
    float mean = g_mean, istd = g_istd, rmax = g_rowmax[i];
    float* mrow = Mio + (size_t)i * N;
    float* prow = g_P0 + (size_t)i * N;
#pragma unroll
    for (int k = 0; k < 16; k++) {
        int j = t + 256 * k;
        float m = mrow[j];
        mrow[j] = (m - mean) * istd;
        prow[j] = __expf((m - rmax) * istd);
    }
}

// ---------------- row matvec: out_i = scale / dot(P0_i, v); also zeros zbuf -----
// mode 0: out=g_u, zbuf=g_z (Sinkhorn).  mode 1: out=g_w, zbuf=g_s (final).
__global__ void k_rowmv(float scale, int gated, int mode) {
    if (gated && g_done) return;
    float* out  = mode ? g_w : g_u;
    float* zbuf = mode ? g_s : g_z;
    if (blockIdx.x < 16) zbuf[blockIdx.x * 256 + threadIdx.x] = 0.f;
    int warp = threadIdx.x >> 5, lane = threadIdx.x & 31;
    int row = blockIdx.x * 8 + warp;
    const float4* prow = (const float4*)(g_P0 + (size_t)row * N);
    const float4* v4 = (const float4*)g_v;
    float acc = 0.f;
#pragma unroll 4
    for (int t = lane; t < 1024; t += 32) {
        float4 p = prow[t];
        float4 vv = __ldg(&v4[t]);
        acc += p.x*vv.x + p.y*vv.y + p.z*vv.z + p.w*vv.w;
    }
    for (int o = 16; o; o >>= 1) acc += __shfl_down_sync(0xffffffffu, acc, o);
    if (lane == 0) out[row] = scale / acc;
}

// ---------------- col matvec: zout_j += sum_i P0[i][j] * uin[i] -----------------
// grid = dim3(2, 256): blockIdx.y -> 16-row stripe, blockIdx.x -> column half.
__global__ void k_colmv(int gated, int mode) {
    if (gated && g_done) return;
    const float* uin = mode ? g_w : g_u;
    float* zout = mode ? g_s : g_z;
    int i0 = blockIdx.y * 16;
    int c0 = blockIdx.x * 512;               // base in float4 units
    int t = threadIdx.x;
    float4 a0 = {0,0,0,0}, a1 = {0,0,0,0};
#pragma unroll
    for (int r = 0; r < 16; r++) {
        float u = __ldg(&uin[i0 + r]);
        const float4* row = (const float4*)(g_P0 + (size_t)(i0 + r) * N) + c0;
        float4 p0 = row[t], p1 = row[t + 256];
        a0.x += p0.x*u; a0.y += p0.y*u; a0.z += p0.z*u; a0.w += p0.w*u;
        a1.x += p1.x*u; a1.y += p1.y*u; a1.z += p1.z*u; a1.w += p1.w*u;
    }
    int j0 = (c0 + t) * 4;
    atomicAdd(&zout[j0+0], a0.x); atomicAdd(&zout[j0+1], a0.y);
    atomicAdd(&zout[j0+2], a0.z); atomicAdd(&zout[j0+3], a0.w);
    int j1 = (c0 + t + 256) * 4;
    atomicAdd(&zout[j1+0], a1.x); atomicAdd(&zout[j1+1], a1.y);
    atomicAdd(&zout[j1+2], a1.z); atomicAdd(&zout[j1+3], a1.w);
}

// ---------------- convergence check + v update ----------------------------------
__global__ void k_check() {
    if (g_done) return;
    int t = threadIdx.x;
    float m = 0.f;
#pragma unroll
    for (int k = 0; k < 16; k++) {
        int j = t + 256 * k;
        m = fmaxf(m, fabsf(g_v[j] * g_z[j] - RC));
    }
    __shared__ float red[256];
    __shared__ int upd;
    red[t] = m; __syncthreads();
    for (int o = 128; o; o >>= 1) { if (t < o) red[t] = fmaxf(red[t], red[t+o]); __syncthreads(); }
    if (t == 0) {
        if (red[0] <= OT_EPS) { g_done = 1; upd = 0; }   // freeze: keep new u, old v
        else upd = 1;
    }
    __syncthreads();
    if (upd) {
#pragma unroll
        for (int k = 0; k < 16; k++) {
            int j = t + 256 * k;
            g_v[j] = RC / g_z[j];
        }
    }
}

// ---------------- sinv_j = 1/s_j -------------------------------------------------
__global__ void k_sinv() {
    int j = blockIdx.x * 256 + threadIdx.x;
    g_sinv[j] = 1.0f / g_s[j];
}

// ---------------- final P = w_i * P0_ij * sinv_j ; loss partials ----------------
__global__ void k_final(float* __restrict__ Pout) {
    int i = blockIdx.x, t = threadIdx.x;
    float wi = g_w[i];
    const float4* row = (const float4*)(g_P0 + (size_t)i * N);
    const float4* sv4 = (const float4*)g_sinv;
    float ss = 0.f;
#pragma unroll
    for (int k = 0; k < 4; k++) {
        int f = t + 256 * k;
        float4 p = row[f];
        float4 si = sv4[f];
        float o0 = wi * p.x * si.x;
        float o1 = wi * p.y * si.y;
        float o2 = wi * p.z * si.z;
        float o3 = wi * p.w * si.w;
        size_t base = (size_t)i * N + (size_t)f * 4;
        Pout[base+0] = o0; Pout[base+1] = o1; Pout[base+2] = o2; Pout[base+3] = o3;
        ss += o0*o0 + o1*o1 + o2*o2 + o3*o3;
        int j = f * 4;
        if (i >= j && i < j + 4) {
            float d = (i == j) ? o0 : (i == j+1) ? o1 : (i == j+2) ? o2 : o3;
            atomicAdd(&g_pdiag, d);
        }
    }
    __shared__ float red[256];
    red[t] = ss; __syncthreads();
    for (int o = 128; o; o >>= 1) { if (t < o) red[t] += red[t+o]; __syncthreads(); }
    if (t == 0) atomicAdd(&g_psum, red[0]);
}

__global__ void k_loss(float* __restrict__ out) {
    out[0] = sqrtf(g_psum - 2.0f * g_pdiag + (float)N);
}

// ---------------- launch ---------------------------------------------------------
extern "C" void kernel_launch(void* const* d_in, const int* in_sizes, int n_in,
                              void* d_out, int out_size) {
    const float* ft = (const float*)d_in[0];
    const float* fs = (const float*)d_in[1];
    float* out  = (float*)d_out;
    float* Pout = out + 1;
    float* Mout = out + 1 + NN;

    k_init<<<1, 256>>>();
    k_rownorms<<<2 * N, 256>>>(ft, fs);
    k_gemm<<<dim3(32, 32), 256>>>(ft, fs, Mout);
    k_stats<<<N, 256>>>(Mout);
    k_stats2<<<1, 1>>>();
    k_makeP0<<<N, 256>>>(Mout);

    for (int it = 0; it < 20; it++) {
        k_rowmv<<<512, 256>>>(RC, 1, 0);        // u = r/(P0 v), zero z
        k_colmv<<<dim3(2, 256), 256>>>(1, 0);   // z = P0^T u
        k_check<<<1, 256>>>();                  // beta check, v = c/z
    }

    k_rowmv<<<512, 256>>>(1.0f, 0, 1);          // w = 1/(P0 v), zero s
    k_colmv<<<dim3(2, 256), 256>>>(0, 1);       // s = P0^T w
    k_sinv<<<16, 256>>>();
    k_final<<<N, 256>>>(Pout);
    k_loss<<<1, 1>>>(out);
}

// round 5
// speedup vs baseline: 1.7287x; 1.7287x over previous
#include <cuda_runtime.h>
#include <cuda_bf16.h>
#include <cstdint>
#include <math.h>

#define N 4096
#define KDIM 1024
#define NN ((size_t)N*(size_t)N)
#define OT_EPS 1e-6f
#define RC (1.0f/4096.0f)

// ======================= PTX helpers (sm_80-level only: no tcgen05!) =======================
__device__ __forceinline__ uint32_t smem_to_u32(const void* smem_ptr) {
    uint32_t addr;
    asm("{ .reg .u64 tmp; cvta.to.shared.u64 tmp, %1; cvt.u32.u64 %0, tmp; }"
        : "=r"(addr) : "l"(smem_ptr));
    return addr;
}
__device__ __forceinline__ void cpasync16(uint32_t dst, const void* src) {
    asm volatile("cp.async.cg.shared.global [%0], [%1], 16;" :: "r"(dst), "l"(src));
}
#define CP_COMMIT() asm volatile("cp.async.commit_group;" ::: "memory")
#define CP_WAIT0()  asm volatile("cp.async.wait_group 0;" ::: "memory")

__device__ __forceinline__ void ldsm4(uint32_t* r, uint32_t addr) {
    asm volatile("ldmatrix.sync.aligned.m8n8.x4.shared.b16 {%0,%1,%2,%3}, [%4];"
        : "=r"(r[0]), "=r"(r[1]), "=r"(r[2]), "=r"(r[3]) : "r"(addr));
}
__device__ __forceinline__ void mma16816(float* d, const uint32_t* a, uint32_t b0, uint32_t b1) {
    asm volatile(
        "mma.sync.aligned.m16n8k16.row.col.f32.bf16.bf16.f32 "
        "{%0,%1,%2,%3}, {%4,%5,%6,%7}, {%8,%9}, {%0,%1,%2,%3};"
        : "+f"(d[0]), "+f"(d[1]), "+f"(d[2]), "+f"(d[3])
        : "r"(a[0]), "r"(a[1]), "r"(a[2]), "r"(a[3]), "r"(b0), "r"(b1));
}

// ======================= device scratch =======================
__device__ float g_P0[16777216];                 // 64 MB: exp(M' - rowmax')
__device__ __nv_bfloat16 g_Abf[4096*3072];       // 24 MB: [A_hi | A_hi | A_lo]
__device__ __nv_bfloat16 g_Bbf[4096*3072];       // 24 MB: [B_hi | B_lo | B_hi]
__device__ float g_u[N], g_v[N], g_z[N], g_w[N], g_s[N], g_sinv[N];
__device__ float g_rowmax[N], g_rinvA[N], g_rinvB[N];
__device__ float g_sum, g_sumsq, g_mean, g_istd, g_psum, g_pdiag;
__device__ int   g_done;

// ======================= init (re-runs on every graph replay) =======================
__global__ void k_init() {
    int t = threadIdx.x;
    if (t == 0) { g_sum = 0.f; g_sumsq = 0.f; g_psum = 0.f; g_pdiag = 0.f; g_done = 0; }
    for (int j = t; j < N; j += 256) { g_v[j] = 1.0f; g_z[j] = 0.f; g_s[j] = 0.f; }
}

// ======================= inverse row norms =======================
__global__ void k_rownorms(const float* __restrict__ ft, const float* __restrict__ fs) {
    int row = blockIdx.x;
    const float* src = (row < N) ? (ft + (size_t)row * KDIM)
                                 : (fs + (size_t)(row - N) * KDIM);
    int t = threadIdx.x;
    float4 v = ((const float4*)src)[t];
    float ss = v.x*v.x + v.y*v.y + v.z*v.z + v.w*v.w;
    __shared__ float red[256];
    red[t] = ss; __syncthreads();
    for (int o = 128; o; o >>= 1) { if (t < o) red[t] += red[t + o]; __syncthreads(); }
    if (t == 0) {
        float inv = 1.0f / fmaxf(sqrtf(red[0]), 1e-12f);
        if (row < N) g_rinvA[row] = inv; else g_rinvB[row - N] = inv;
    }
}

// ======================= bf16-split conversion (normalized rows) =======================
// A' K-slices: [hi, hi, lo] ; B' K-slices: [hi, lo, hi]
// A'.B'^T over K=3072 = ah*bh + ah*bl + al*bh   (drops only the ~2^-18 al*bl term)
__global__ void k_convert(const float* __restrict__ ft, const float* __restrict__ fs) {
    int row = blockIdx.x;
    int t = threadIdx.x;
    bool isA = row < N;
    int r = isA ? row : row - N;
    const float* src = (isA ? ft : fs) + (size_t)r * KDIM;
    float rinv = isA ? g_rinvA[r] : g_rinvB[r];
    __nv_bfloat16* dst = (isA ? g_Abf : g_Bbf) + (size_t)r * 3072;
    float4 v = ((const float4*)src)[t];
    float x0 = v.x * rinv, x1 = v.y * rinv, x2 = v.z * rinv, x3 = v.w * rinv;
    __nv_bfloat16 h0 = __float2bfloat16(x0), h1 = __float2bfloat16(x1);
    __nv_bfloat16 h2 = __float2bfloat16(x2), h3 = __float2bfloat16(x3);
    __nv_bfloat16 l0 = __float2bfloat16(x0 - __bfloat162float(h0));
    __nv_bfloat16 l1 = __float2bfloat16(x1 - __bfloat162float(h1));
    __nv_bfloat16 l2 = __float2bfloat16(x2 - __bfloat162float(h2));
    __nv_bfloat16 l3 = __float2bfloat16(x3 - __bfloat162float(h3));
    __nv_bfloat162 hh0, hh1, ll0, ll1;
    hh0.x = h0; hh0.y = h1; hh1.x = h2; hh1.y = h3;
    ll0.x = l0; ll0.y = l1; ll1.x = l2; ll1.y = l3;
    __nv_bfloat162* d2 = (__nv_bfloat162*)dst;
    int c2 = t * 2;
    d2[c2] = hh0; d2[c2 + 1] = hh1;                       // slice 0: hi
    if (isA) {
        d2[512 + c2] = hh0; d2[512 + c2 + 1] = hh1;       // slice 1: hi
        d2[1024 + c2] = ll0; d2[1024 + c2 + 1] = ll1;     // slice 2: lo
    } else {
        d2[512 + c2] = ll0; d2[512 + c2 + 1] = ll1;       // slice 1: lo
        d2[1024 + c2] = hh0; d2[1024 + c2 + 1] = hh1;     // slice 2: hi
    }
}

// ======================= mma.sync bf16 GEMM: M = A' @ B'^T, K=3072 =======================
// 128x128 block tile, 8 warps (2x4), warp tile 64x32, K-chunk 64 (128B rows, XOR swizzle),
// double-buffered smem via cp.async. Epilogue uses SCALAR stores: Mout is only
// 4-byte aligned (d_out + 1 float) — vector stores trap.
#define G_NCH 48                 // 3072 / 64
#define G_STAGE 32768            // A 16KB + B 16KB
#define GEMM_SMEM 65536

__global__ void __launch_bounds__(256) k_gemm_mma(float* __restrict__ Mout) {
    extern __shared__ char sm[];
    uint32_t smb = smem_to_u32(sm);
    int tid = threadIdx.x, wid = tid >> 5, lane = tid & 31;
    int bx = blockIdx.x, by = blockIdx.y;
    const char* Ag = (const char*)g_Abf + (size_t)by * 128 * 6144;
    const char* Bg = (const char*)g_Bbf + (size_t)bx * 128 * 6144;

    // load mapping: thread covers rows r_, r_+32, r_+64, r_+96 at 16B column q16
    int r_  = tid >> 3;
    int q16 = (tid & 7) * 16;
    int sw_ = r_ * 128 + (q16 ^ ((r_ & 7) << 4));      // swizzle = col16 ^ (row&7)

    // preload chunk 0 into stage 0
#pragma unroll
    for (int l = 0; l < 4; l++) {
        uint32_t so = sw_ + l * 4096;
        size_t   go = (size_t)(r_ + l * 32) * 6144 + q16;
        cpasync16(smb + so,        Ag + go);
        cpasync16(smb + 16384 + so, Bg + go);
    }
    CP_COMMIT(); CP_WAIT0();
    __syncthreads();

    int wm = wid & 1, wn = wid >> 1;                   // warp grid 2(M) x 4(N)
    int la15 = lane & 15, khalf = (lane >> 4) * 16;

    float acc[4][4][4];
#pragma unroll
    for (int ma = 0; ma < 4; ma++)
#pragma unroll
        for (int na = 0; na < 4; na++)
#pragma unroll
            for (int i = 0; i < 4; i++) acc[ma][na][i] = 0.f;

#pragma unroll 1
    for (int c = 0; c < G_NCH; c++) {
        uint32_t base = smb + (c & 1) * G_STAGE;
        if (c + 1 < G_NCH) {
            uint32_t dst = smb + ((c + 1) & 1) * G_STAGE;
            size_t kb = (size_t)(c + 1) * 128;
#pragma unroll
            for (int l = 0; l < 4; l++) {
                uint32_t so = sw_ + l * 4096;
                size_t   go = (size_t)(r_ + l * 32) * 6144 + kb + q16;
                cpasync16(dst + so,        Ag + go);
                cpasync16(dst + 16384 + so, Bg + go);
            }
            CP_COMMIT();
        }
#pragma unroll
        for (int k16 = 0; k16 < 4; k16++) {
            int cb = k16 * 32 + khalf;
            uint32_t a[4][4], b[2][4];
#pragma unroll
            for (int ma = 0; ma < 4; ma++) {
                int r = wm * 64 + ma * 16 + la15;
                ldsm4(a[ma], base + r * 128 + (cb ^ ((r & 7) << 4)));
            }
#pragma unroll
            for (int nb = 0; nb < 2; nb++) {
                int r = wn * 32 + nb * 16 + la15;
                ldsm4(b[nb], base + 16384 + r * 128 + (cb ^ ((r & 7) << 4)));
            }
#pragma unroll
            for (int ma = 0; ma < 4; ma++)
#pragma unroll
                for (int na = 0; na < 4; na++)
                    mma16816(acc[ma][na], a[ma], b[na >> 1][na & 1], b[na >> 1][(na & 1) + 2]);
        }
        if (c + 1 < G_NCH) CP_WAIT0();
        __syncthreads();
    }

    // epilogue: fragment (gid=lane>>2 row, tig=lane&3 col-pair) — SCALAR stores only
    int gid = lane >> 2, tig = lane & 3;
#pragma unroll
    for (int ma = 0; ma < 4; ma++) {
#pragma unroll
        for (int na = 0; na < 4; na++) {
            int row = by * 128 + wm * 64 + ma * 16 + gid;
            int col = bx * 128 + wn * 32 + na * 8 + tig * 2;
            float* p0 = Mout + (size_t)row * 4096 + col;
            float* p1 = Mout + (size_t)(row + 8) * 4096 + col;
            p0[0] = acc[ma][na][0]; p0[1] = acc[ma][na][1];
            p1[0] = acc[ma][na][2]; p1[1] = acc[ma][na][3];
        }
    }
}

// ======================= stats over raw M =======================
__global__ void k_stats(const float* __restrict__ Mraw) {
    int i = blockIdx.x, t = threadIdx.x;
    const float* row = Mraw + (size_t)i * N;
    float s = 0.f, s2 = 0.f, mx = -1e30f;
#pragma unroll
    for (int k = 0; k < 16; k++) {
        float v = row[t + 256 * k];
        s += v; s2 += v * v; mx = fmaxf(mx, v);
    }
    __shared__ float rs[256], rq[256], rm[256];
    rs[t] = s; rq[t] = s2; rm[t] = mx; __syncthreads();
    for (int o = 128; o; o >>= 1) {
        if (t < o) { rs[t] += rs[t+o]; rq[t] += rq[t+o]; rm[t] = fmaxf(rm[t], rm[t+o]); }
        __syncthreads();
    }
    if (t == 0) {
        atomicAdd(&g_sum, rs[0]);
        atomicAdd(&g_sumsq, rq[0]);
        g_rowmax[i] = rm[0];
    }
}

__global__ void k_stats2() {
    double s = (double)g_sum, s2 = (double)g_sumsq;
    double n = (double)NN;
    double mean = s / n;
    double var = (s2 - n * mean * mean) / (n - 1.0);   // ddof=1
    g_mean = (float)mean;
    g_istd = (float)(1.0 / sqrt(var));
}

// ======================= standardize M in place, build P0 =======================
__global__ void k_makeP0(float* __restrict__ Mio) {
    int i = blockIdx.x, t = threadIdx.x;
    float mean = g_mean, istd = g_istd, rmax = g_rowmax[i];
    float* mrow = Mio + (size_t)i * N;
    float* prow = g_P0 + (size_t)i * N;
#pragma unroll
    for (int k = 0; k < 16; k++) {
        int j = t + 256 * k;
        float m = mrow[j];
        mrow[j] = (m - mean) * istd;
        prow[j] = __expf((m - rmax) * istd);
    }
}

// ======================= fused Sinkhorn half-iteration (persistent) =======================
// 128 blocks x 4 stripes of 8 rows. Per stripe: stage rows in smem, u_i = scale/(P0_i.v),
// accumulate z-partials in registers across stripes; single atomicAdd pass at the end.
// mode 0: out=g_u, z=g_z (loop, gated).  mode 1: out=g_w, z=g_s (final).
__global__ void __launch_bounds__(256) k_sink(float scale, int gated, int mode) {
    if (gated && g_done) return;
    extern __shared__ float smrows[];          // 8 * 4096 floats = 128 KB
    __shared__ float su[8];
    int t = threadIdx.x, w = t >> 5, lane = t & 31;
    float* outv = mode ? g_w : g_u;
    float* zb   = mode ? g_s : g_z;
    const float4* v4 = (const float4*)g_v;
    float4 za[4];
#pragma unroll
    for (int kk = 0; kk < 4; kk++) za[kk] = make_float4(0.f, 0.f, 0.f, 0.f);

    for (int st = blockIdx.x; st < 512; st += 128) {
        int i0 = st * 8;
        {
            const float4* row4 = (const float4*)(g_P0 + (size_t)(i0 + w) * N);
            float4* srow = (float4*)(smrows + (size_t)w * N);
            float a = 0.f;
#pragma unroll 4
            for (int q = lane; q < 1024; q += 32) {
                float4 p = row4[q];
                srow[q] = p;
                float4 vv = v4[q];
                a += p.x*vv.x + p.y*vv.y + p.z*vv.z + p.w*vv.w;
            }
            for (int o = 16; o; o >>= 1) a += __shfl_down_sync(0xffffffffu, a, o);
            if (lane == 0) {
                float uu = scale / a;
                su[w] = uu;
                outv[i0 + w] = uu;
            }
        }
        __syncthreads();
        const float4* sm4 = (const float4*)smrows;
#pragma unroll
        for (int kk = 0; kk < 4; kk++) {
            int j4 = t + kk * 256;
#pragma unroll
            for (int r = 0; r < 8; r++) {
                float4 p = sm4[(size_t)r * 1024 + j4];
                float ur = su[r];
                za[kk].x += p.x * ur; za[kk].y += p.y * ur;
                za[kk].z += p.z * ur; za[kk].w += p.w * ur;
            }
        }
        __syncthreads();
    }
#pragma unroll
    for (int kk = 0; kk < 4; kk++) {
        int j = (t + kk * 256) * 4;
        atomicAdd(&zb[j + 0], za[kk].x); atomicAdd(&zb[j + 1], za[kk].y);
        atomicAdd(&zb[j + 2], za[kk].z); atomicAdd(&zb[j + 3], za[kk].w);
    }
}

// ======================= convergence check + v update + z re-zero =======================
__global__ void k_check() {
    if (g_done) return;
    int t = threadIdx.x;
    float m = 0.f;
#pragma unroll
    for (int k = 0; k < 16; k++) {
        int j = t + 256 * k;
        m = fmaxf(m, fabsf(g_v[j] * g_z[j] - RC));
    }
    __shared__ float red[256];
    __shared__ int upd;
    red[t] = m; __syncthreads();
    for (int o = 128; o; o >>= 1) { if (t < o) red[t] = fmaxf(red[t], red[t+o]); __syncthreads(); }
    if (t == 0) {
        if (red[0] <= OT_EPS) { g_done = 1; upd = 0; }
        else upd = 1;
    }
    __syncthreads();
    if (upd) {
#pragma unroll
        for (int k = 0; k < 16; k++) {
            int j = t + 256 * k;
            g_v[j] = RC / g_z[j];
            g_z[j] = 0.f;
        }
    }
}

__global__ void k_sinv() {
    int j = blockIdx.x * 256 + threadIdx.x;
    g_sinv[j] = 1.0f / g_s[j];
}

// ======================= final P = w_i * P0_ij * sinv_j ; loss partials =======================
// Pout is only 4-byte aligned (d_out + 1 float) — scalar stores only.
__global__ void k_final(float* __restrict__ Pout) {
    int i = blockIdx.x, t = threadIdx.x;
    float wi = g_w[i];
    const float4* row = (const float4*)(g_P0 + (size_t)i * N);
    const float4* sv4 = (const float4*)g_sinv;
    float ss = 0.f;
#pragma unroll
    for (int k = 0; k < 4; k++) {
        int f = t + 256 * k;
        float4 p = row[f];
        float4 si = sv4[f];
        float o0 = wi * p.x * si.x;
        float o1 = wi * p.y * si.y;
        float o2 = wi * p.z * si.z;
        float o3 = wi * p.w * si.w;
        size_t base = (size_t)i * N + (size_t)f * 4;
        Pout[base+0] = o0; Pout[base+1] = o1; Pout[base+2] = o2; Pout[base+3] = o3;
        ss += o0*o0 + o1*o1 + o2*o2 + o3*o3;
        int j = f * 4;
        if (i >= j && i < j + 4) {
            float d = (i == j) ? o0 : (i == j+1) ? o1 : (i == j+2) ? o2 : o3;
            atomicAdd(&g_pdiag, d);
        }
    }
    __shared__ float red[256];
    red[t] = ss; __syncthreads();
    for (int o = 128; o; o >>= 1) { if (t < o) red[t] += red[t+o]; __syncthreads(); }
    if (t == 0) atomicAdd(&g_psum, red[0]);
}

__global__ void k_loss(float* __restrict__ out) {
    out[0] = sqrtf(g_psum - 2.0f * g_pdiag + (float)N);
}

// ======================= launch =======================
extern "C" void kernel_launch(void* const* d_in, const int* in_sizes, int n_in,
                              void* d_out, int out_size) {
    const float* ft = (const float*)d_in[0];
    const float* fs = (const float*)d_in[1];
    float* out  = (float*)d_out;
    float* Pout = out + 1;
    float* Mout = out + 1 + NN;

    cudaFuncSetAttribute(k_gemm_mma, cudaFuncAttributeMaxDynamicSharedMemorySize, GEMM_SMEM);
    cudaFuncSetAttribute(k_sink,     cudaFuncAttributeMaxDynamicSharedMemorySize, 131072);

    k_init<<<1, 256>>>();
    k_rownorms<<<2 * N, 256>>>(ft, fs);
    k_convert<<<2 * N, 256>>>(ft, fs);
    k_gemm_mma<<<dim3(32, 32), 256, GEMM_SMEM>>>(Mout);
    k_stats<<<N, 256>>>(Mout);
    k_stats2<<<1, 1>>>();
    k_makeP0<<<N, 256>>>(Mout);

    for (int it = 0; it < 20; it++) {
        k_sink<<<128, 256, 131072>>>(RC, 1, 0);   // u = r/(P0 v), z = P0^T u
        k_check<<<1, 256>>>();                    // beta check, v = c/z, z = 0
    }

    k_sink<<<128, 256, 131072>>>(1.0f, 0, 1);     // w = 1/(P0 v), s = P0^T w
    k_sinv<<<16, 256>>>();
    k_final<<<N, 256>>>(Pout);
    k_loss<<<1, 1>>>(out);
}

// round 6
// speedup vs baseline: 1.9472x; 1.1264x over previous
#include <cuda_runtime.h>
#include <cuda_bf16.h>
#include <cuda_fp16.h>
#include <cstdint>
#include <math.h>

#define N 4096
#define KDIM 1024
#define NN ((size_t)N*(size_t)N)
#define OT_EPS 1e-6f
#define RC (1.0f/4096.0f)
#define NB 128                   // persistent sinkhorn blocks (<= #SMs, all co-resident)

// ======================= PTX helpers (sm_80-level only: no tcgen05!) =======================
__device__ __forceinline__ uint32_t smem_to_u32(const void* smem_ptr) {
    uint32_t addr;
    asm("{ .reg .u64 tmp; cvta.to.shared.u64 tmp, %1; cvt.u32.u64 %0, tmp; }"
        : "=r"(addr) : "l"(smem_ptr));
    return addr;
}
__device__ __forceinline__ void cpasync16(uint32_t dst, const void* src) {
    asm volatile("cp.async.cg.shared.global [%0], [%1], 16;" :: "r"(dst), "l"(src));
}
#define CP_COMMIT() asm volatile("cp.async.commit_group;" ::: "memory")
#define CP_WAIT0()  asm volatile("cp.async.wait_group 0;" ::: "memory")
#define CP_WAIT1()  asm volatile("cp.async.wait_group 1;" ::: "memory")

__device__ __forceinline__ void ldsm4(uint32_t* r, uint32_t addr) {
    asm volatile("ldmatrix.sync.aligned.m8n8.x4.shared.b16 {%0,%1,%2,%3}, [%4];"
        : "=r"(r[0]), "=r"(r[1]), "=r"(r[2]), "=r"(r[3]) : "r"(addr));
}
__device__ __forceinline__ void mma16816(float* d, const uint32_t* a, uint32_t b0, uint32_t b1) {
    asm volatile(
        "mma.sync.aligned.m16n8k16.row.col.f32.bf16.bf16.f32 "
        "{%0,%1,%2,%3}, {%4,%5,%6,%7}, {%8,%9}, {%0,%1,%2,%3};"
        : "+f"(d[0]), "+f"(d[1]), "+f"(d[2]), "+f"(d[3])
        : "r"(a[0]), "r"(a[1]), "r"(a[2]), "r"(a[3]), "r"(b0), "r"(b1));
}

// monotonic uint encoding for float atomicMax
__device__ __forceinline__ unsigned fenc(float f) {
    unsigned u = __float_as_uint(f);
    return (u & 0x80000000u) ? ~u : (u | 0x80000000u);
}
__device__ __forceinline__ float fdec(unsigned u) {
    return (u & 0x80000000u) ? __uint_as_float(u & 0x7fffffffu) : __uint_as_float(~u);
}

// ======================= device scratch =======================
__device__ __half g_P0h[16777216];               // 32 MB: exp(M' - rowmax') in fp16
__device__ __nv_bfloat16 g_Abf[4096*3072];       // 24 MB: [A_hi | A_hi | A_lo]
__device__ __nv_bfloat16 g_Bbf[4096*3072];       // 24 MB: [B_hi | B_lo | B_hi]
__device__ float g_zbuf[2][N];
__device__ float g_w[N], g_s[N], g_sinv[N];
__device__ unsigned g_rowmax_u[N];
__device__ float g_rinvA[N], g_rinvB[N];
__device__ float g_sum, g_sumsq, g_mean, g_istd, g_psum, g_pdiag;
__device__ unsigned g_barcnt;
__device__ volatile unsigned g_bargen;

// DIY grid barrier: all NB blocks must be co-resident (NB <= SM count, 1 block/SM fits).
__device__ __forceinline__ void gbar() {
    __syncthreads();
    if (threadIdx.x == 0) {
        __threadfence();
        unsigned arr = atomicAdd(&g_barcnt, 1u) + 1u;
        unsigned gen = (arr + NB - 1u) / NB;
        if (arr == gen * NB) {
            g_bargen = gen;
        } else {
            while (g_bargen < gen) { }
        }
    }
    __syncthreads();
}

// ======================= init (re-runs on every graph replay) =======================
__global__ void k_init() {
    int gid = blockIdx.x * 256 + threadIdx.x;
    if (gid == 0) {
        g_sum = 0.f; g_sumsq = 0.f; g_psum = 0.f; g_pdiag = 0.f;
        g_barcnt = 0u; g_bargen = 0u;
    }
    if (gid < N) {
        g_zbuf[0][gid] = 0.f; g_zbuf[1][gid] = 0.f;
        g_s[gid] = 0.f; g_rowmax_u[gid] = 0u;
    }
}

// ======================= inverse row norms =======================
__global__ void k_rownorms(const float* __restrict__ ft, const float* __restrict__ fs) {
    int row = blockIdx.x;
    const float* src = (row < N) ? (ft + (size_t)row * KDIM)
                                 : (fs + (size_t)(row - N) * KDIM);
    int t = threadIdx.x;
    float4 v = ((const float4*)src)[t];
    float ss = v.x*v.x + v.y*v.y + v.z*v.z + v.w*v.w;
    __shared__ float red[256];
    red[t] = ss; __syncthreads();
    for (int o = 128; o; o >>= 1) { if (t < o) red[t] += red[t + o]; __syncthreads(); }
    if (t == 0) {
        float inv = 1.0f / fmaxf(sqrtf(red[0]), 1e-12f);
        if (row < N) g_rinvA[row] = inv; else g_rinvB[row - N] = inv;
    }
}

// ======================= bf16-split conversion (normalized rows) =======================
// A' K-slices: [hi, hi, lo] ; B' K-slices: [hi, lo, hi]
__global__ void k_convert(const float* __restrict__ ft, const float* __restrict__ fs) {
    int row = blockIdx.x;
    int t = threadIdx.x;
    bool isA = row < N;
    int r = isA ? row : row - N;
    const float* src = (isA ? ft : fs) + (size_t)r * KDIM;
    float rinv = isA ? g_rinvA[r] : g_rinvB[r];
    __nv_bfloat16* dst = (isA ? g_Abf : g_Bbf) + (size_t)r * 3072;
    float4 v = ((const float4*)src)[t];
    float x0 = v.x * rinv, x1 = v.y * rinv, x2 = v.z * rinv, x3 = v.w * rinv;
    __nv_bfloat16 h0 = __float2bfloat16(x0), h1 = __float2bfloat16(x1);
    __nv_bfloat16 h2 = __float2bfloat16(x2), h3 = __float2bfloat16(x3);
    __nv_bfloat16 l0 = __float2bfloat16(x0 - __bfloat162float(h0));
    __nv_bfloat16 l1 = __float2bfloat16(x1 - __bfloat162float(h1));
    __nv_bfloat16 l2 = __float2bfloat16(x2 - __bfloat162float(h2));
    __nv_bfloat16 l3 = __float2bfloat16(x3 - __bfloat162float(h3));
    __nv_bfloat162 hh0, hh1, ll0, ll1;
    hh0.x = h0; hh0.y = h1; hh1.x = h2; hh1.y = h3;
    ll0.x = l0; ll0.y = l1; ll1.x = l2; ll1.y = l3;
    __nv_bfloat162* d2 = (__nv_bfloat162*)dst;
    int c2 = t * 2;
    d2[c2] = hh0; d2[c2 + 1] = hh1;                       // slice 0: hi
    if (isA) {
        d2[512 + c2] = hh0; d2[512 + c2 + 1] = hh1;       // slice 1: hi
        d2[1024 + c2] = ll0; d2[1024 + c2 + 1] = ll1;     // slice 2: lo
    } else {
        d2[512 + c2] = ll0; d2[512 + c2 + 1] = ll1;       // slice 1: lo
        d2[1024 + c2] = hh0; d2[1024 + c2 + 1] = hh1;     // slice 2: hi
    }
}

// ======================= mma.sync bf16 GEMM + fused stats, K=3072 =======================
// 128x128 tile, 8 warps (2x4), warp 64x32, K-chunk 64, 3-stage cp.async pipeline.
// Epilogue: scalar stores (Mout only 4B aligned) + per-CTA sum/sumsq/rowmax partials.
#define G_NCH 48
#define G_STAGE 32768
#define GEMM_SMEM (3 * G_STAGE)

__global__ void __launch_bounds__(256) k_gemm_mma(float* __restrict__ Mout) {
    extern __shared__ char sm[];
    uint32_t smb = smem_to_u32(sm);
    int tid = threadIdx.x, wid = tid >> 5, lane = tid & 31;
    int bx = blockIdx.x, by = blockIdx.y;
    const char* Ag = (const char*)g_Abf + (size_t)by * 128 * 6144;
    const char* Bg = (const char*)g_Bbf + (size_t)bx * 128 * 6144;

    int r_  = tid >> 3;
    int q16 = (tid & 7) * 16;
    int sw_ = r_ * 128 + (q16 ^ ((r_ & 7) << 4));

    // preload chunks 0 and 1 (separate commit groups)
#pragma unroll
    for (int pc = 0; pc < 2; pc++) {
        uint32_t dst = smb + pc * G_STAGE;
        size_t kb = (size_t)pc * 128;
#pragma unroll
        for (int l = 0; l < 4; l++) {
            uint32_t so = sw_ + l * 4096;
            size_t   go = (size_t)(r_ + l * 32) * 6144 + kb + q16;
            cpasync16(dst + so,         Ag + go);
            cpasync16(dst + 16384 + so, Bg + go);
        }
        CP_COMMIT();
    }

    int wm = wid & 1, wn = wid >> 1;
    int la15 = lane & 15, khalf = (lane >> 4) * 16;

    float acc[4][4][4];
#pragma unroll
    for (int ma = 0; ma < 4; ma++)
#pragma unroll
        for (int na = 0; na < 4; na++)
#pragma unroll
            for (int i = 0; i < 4; i++) acc[ma][na][i] = 0.f;

#pragma unroll 1
    for (int c = 0; c < G_NCH; c++) {
        if (c + 2 < G_NCH) { CP_WAIT1(); } else { CP_WAIT0(); }
        __syncthreads();
        if (c + 2 < G_NCH) {
            uint32_t dst = smb + ((c + 2) % 3) * G_STAGE;
            size_t kb = (size_t)(c + 2) * 128;
#pragma unroll
            for (int l = 0; l < 4; l++) {
                uint32_t so = sw_ + l * 4096;
                size_t   go = (size_t)(r_ + l * 32) * 6144 + kb + q16;
                cpasync16(dst + so,         Ag + go);
                cpasync16(dst + 16384 + so, Bg + go);
            }
            CP_COMMIT();
        }
        uint32_t base = smb + (c % 3) * G_STAGE;
#pragma unroll
        for (int k16 = 0; k16 < 4; k16++) {
            int cb = k16 * 32 + khalf;
            uint32_t a[4][4], b[2][4];
#pragma unroll
            for (int ma = 0; ma < 4; ma++) {
                int r = wm * 64 + ma * 16 + la15;
                ldsm4(a[ma], base + r * 128 + (cb ^ ((r & 7) << 4)));
            }
#pragma unroll
            for (int nb = 0; nb < 2; nb++) {
                int r = wn * 32 + nb * 16 + la15;
                ldsm4(b[nb], base + 16384 + r * 128 + (cb ^ ((r & 7) << 4)));
            }
#pragma unroll
            for (int ma = 0; ma < 4; ma++)
#pragma unroll
                for (int na = 0; na < 4; na++)
                    mma16816(acc[ma][na], a[ma], b[na >> 1][na & 1], b[na >> 1][(na & 1) + 2]);
        }
    }

    // ---- epilogue: scalar stores + fused stats ----
    int gid = lane >> 2, tig = lane & 3;
    float tsum = 0.f, tsq = 0.f;
#pragma unroll
    for (int ma = 0; ma < 4; ma++) {
        float rm0 = -1e30f, rm1 = -1e30f;
        int row = by * 128 + wm * 64 + ma * 16 + gid;
#pragma unroll
        for (int na = 0; na < 4; na++) {
            int col = bx * 128 + wn * 32 + na * 8 + tig * 2;
            float a0 = acc[ma][na][0], a1 = acc[ma][na][1];
            float a2 = acc[ma][na][2], a3 = acc[ma][na][3];
            float* p0 = Mout + (size_t)row * 4096 + col;
            float* p1 = Mout + (size_t)(row + 8) * 4096 + col;
            p0[0] = a0; p0[1] = a1; p1[0] = a2; p1[1] = a3;
            tsum += (a0 + a1) + (a2 + a3);
            tsq  += a0*a0 + a1*a1 + a2*a2 + a3*a3;
            rm0 = fmaxf(rm0, fmaxf(a0, a1));
            rm1 = fmaxf(rm1, fmaxf(a2, a3));
        }
        rm0 = fmaxf(rm0, __shfl_xor_sync(0xffffffffu, rm0, 1));
        rm0 = fmaxf(rm0, __shfl_xor_sync(0xffffffffu, rm0, 2));
        rm1 = fmaxf(rm1, __shfl_xor_sync(0xffffffffu, rm1, 1));
        rm1 = fmaxf(rm1, __shfl_xor_sync(0xffffffffu, rm1, 2));
        if (tig == 0) {
            atomicMax(&g_rowmax_u[row], fenc(rm0));
            atomicMax(&g_rowmax_u[row + 8], fenc(rm1));
        }
    }
    __shared__ float rsum[256], rsq[256];
    rsum[tid] = tsum; rsq[tid] = tsq; __syncthreads();
    for (int o = 128; o; o >>= 1) {
        if (tid < o) { rsum[tid] += rsum[tid + o]; rsq[tid] += rsq[tid + o]; }
        __syncthreads();
    }
    if (tid == 0) { atomicAdd(&g_sum, rsum[0]); atomicAdd(&g_sumsq, rsq[0]); }
}

__global__ void k_stats2() {
    double s = (double)g_sum, s2 = (double)g_sumsq;
    double n = (double)NN;
    double mean = s / n;
    double var = (s2 - n * mean * mean) / (n - 1.0);   // ddof=1
    g_mean = (float)mean;
    g_istd = (float)(1.0 / sqrt(var));
}

// ======================= standardize M in place, build fp16 P0 =======================
__global__ void k_makeP0(float* __restrict__ Mio) {
    int i = blockIdx.x, t = threadIdx.x;
    float mean = g_mean, istd = g_istd;
    float rmax = fdec(g_rowmax_u[i]);
    float* mrow = Mio + (size_t)i * N;
    __half2* prow = (__half2*)(g_P0h + (size_t)i * N);
#pragma unroll
    for (int k = 0; k < 8; k++) {
        int jp = t + 256 * k;                // pair index
        float m0 = mrow[2*jp], m1 = mrow[2*jp + 1];
        mrow[2*jp]     = (m0 - mean) * istd;
        mrow[2*jp + 1] = (m1 - mean) * istd;
        float e0 = __expf((m0 - rmax) * istd);
        float e1 = __expf((m1 - rmax) * istd);
        prow[jp] = __floats2half2_rn(e0, e1);
    }
}

// ======================= persistent fused Sinkhorn (all 20 iters + final w/s pass) =======
// NB blocks x 256 threads, grid barrier between phases. v lives in smem (identical in
// every block; all blocks make identical convergence decisions -> consistent control flow).
__global__ void __launch_bounds__(256) k_sinkall() {
    extern __shared__ char smraw[];
    float* v_sm = (float*)smraw;                           // 4096 floats  (16 KB)
    __half2* smrows = (__half2*)(smraw + 16384);           // 8 rows x 2048 half2 (64 KB)
    __shared__ float su[8];
    __shared__ float red[256];
    int t = threadIdx.x, w = t >> 5, lane = t & 31;

    for (int j = t; j < N; j += 256) v_sm[j] = 1.0f;
    __syncthreads();

    const float2* v2 = (const float2*)v_sm;
    int done = 0, p = 0;

    for (int it = 0; it < 20 && !done; it++) {
        float za[16];
#pragma unroll
        for (int q = 0; q < 16; q++) za[q] = 0.f;

        for (int st = blockIdx.x; st < 512; st += NB) {
            int i0 = st * 8;
            {   // row pass: warp w -> row i0+w; stage row in smem, dot with v
                const __half2* row = (const __half2*)(g_P0h + (size_t)(i0 + w) * N);
                __half2* srow = smrows + (size_t)w * 2048;
                float acc = 0.f;
#pragma unroll 8
                for (int q = lane; q < 2048; q += 32) {
                    __half2 h = row[q];
                    srow[q] = h;
                    float2 f = __half22float2(h);
                    float2 vv = v2[q];
                    acc += f.x * vv.x + f.y * vv.y;
                }
#pragma unroll
                for (int o = 16; o; o >>= 1) acc += __shfl_down_sync(0xffffffffu, acc, o);
                if (lane == 0) su[w] = RC / acc;
            }
            __syncthreads();
#pragma unroll
            for (int kk = 0; kk < 8; kk++) {
                int j2 = t + kk * 256;
#pragma unroll
                for (int r = 0; r < 8; r++) {
                    float2 f = __half22float2(smrows[(size_t)r * 2048 + j2]);
                    float ur = su[r];
                    za[kk*2]     += f.x * ur;
                    za[kk*2 + 1] += f.y * ur;
                }
            }
            __syncthreads();
        }
        float* zb = g_zbuf[p];
#pragma unroll
        for (int kk = 0; kk < 8; kk++) {
            int j = (t + kk * 256) * 2;
            atomicAdd(&zb[j], za[kk*2]);
            atomicAdd(&zb[j + 1], za[kk*2 + 1]);
        }
        gbar();
        // phase 2: convergence check + v update (redundant in all blocks) + zero other buf
        float md = 0.f;
        float znew[16];
#pragma unroll
        for (int kk = 0; kk < 16; kk++) {
            int j = t + kk * 256;
            float zj = __ldcg(&g_zbuf[p][j]);
            znew[kk] = zj;
            md = fmaxf(md, fabsf(v_sm[j] * zj - RC));
        }
        red[t] = md; __syncthreads();
        for (int o = 128; o; o >>= 1) {
            if (t < o) red[t] = fmaxf(red[t], red[t + o]);
            __syncthreads();
        }
        md = red[0];
        int newdone = done | (md <= OT_EPS);
        if (!newdone) {
#pragma unroll
            for (int kk = 0; kk < 16; kk++) {
                int j = t + kk * 256;
                v_sm[j] = RC / znew[kk];
            }
        }
        done = newdone;
        if (t < 32) __stcg(&g_zbuf[p ^ 1][blockIdx.x * 32 + t], 0.f);
        gbar();
        p ^= 1;
    }

    // final pass: w_i = 1/(P0 v)_i ; s = P0^T w
    float sa[16];
#pragma unroll
    for (int q = 0; q < 16; q++) sa[q] = 0.f;
    for (int st = blockIdx.x; st < 512; st += NB) {
        int i0 = st * 8;
        {
            const __half2* row = (const __half2*)(g_P0h + (size_t)(i0 + w) * N);
            __half2* srow = smrows + (size_t)w * 2048;
            float acc = 0.f;
#pragma unroll 8
            for (int q = lane; q < 2048; q += 32) {
                __half2 h = row[q];
                srow[q] = h;
                float2 f = __half22float2(h);
                float2 vv = v2[q];
                acc += f.x * vv.x + f.y * vv.y;
            }
#pragma unroll
            for (int o = 16; o; o >>= 1) acc += __shfl_down_sync(0xffffffffu, acc, o);
            if (lane == 0) { float uu = 1.0f / acc; su[w] = uu; g_w[i0 + w] = uu; }
        }
        __syncthreads();
#pragma unroll
        for (int kk = 0; kk < 8; kk++) {
            int j2 = t + kk * 256;
#pragma unroll
            for (int r = 0; r < 8; r++) {
                float2 f = __half22float2(smrows[(size_t)r * 2048 + j2]);
                float ur = su[r];
                sa[kk*2]     += f.x * ur;
                sa[kk*2 + 1] += f.y * ur;
            }
        }
        __syncthreads();
    }
#pragma unroll
    for (int kk = 0; kk < 8; kk++) {
        int j = (t + kk * 256) * 2;
        atomicAdd(&g_s[j], sa[kk*2]);
        atomicAdd(&g_s[j + 1], sa[kk*2 + 1]);
    }
}

__global__ void k_sinv() {
    int j = blockIdx.x * 256 + threadIdx.x;
    g_sinv[j] = 1.0f / g_s[j];
}

// ======================= final P = w_i * P0_ij * sinv_j ; loss partials =======================
__global__ void k_final(float* __restrict__ Pout) {
    int i = blockIdx.x, t = threadIdx.x;
    float wi = g_w[i];
    const __half2* row = (const __half2*)(g_P0h + (size_t)i * N);
    const float2* sv2 = (const float2*)g_sinv;
    float ss = 0.f;
#pragma unroll
    for (int k = 0; k < 8; k++) {
        int jp = t + 256 * k;
        float2 f = __half22float2(row[jp]);
        float2 si = sv2[jp];
        float o0 = wi * f.x * si.x;
        float o1 = wi * f.y * si.y;
        size_t base = (size_t)i * N + (size_t)jp * 2;
        Pout[base] = o0; Pout[base + 1] = o1;
        ss += o0*o0 + o1*o1;
        int j = jp * 2;
        if (i == j) atomicAdd(&g_pdiag, o0);
        else if (i == j + 1) atomicAdd(&g_pdiag, o1);
    }
    __shared__ float red[256];
    red[t] = ss; __syncthreads();
    for (int o = 128; o; o >>= 1) { if (t < o) red[t] += red[t + o]; __syncthreads(); }
    if (t == 0) atomicAdd(&g_psum, red[0]);
}

__global__ void k_loss(float* __restrict__ out) {
    out[0] = sqrtf(g_psum - 2.0f * g_pdiag + (float)N);
}

// ======================= launch =======================
extern "C" void kernel_launch(void* const* d_in, const int* in_sizes, int n_in,
                              void* d_out, int out_size) {
    const float* ft = (const float*)d_in[0];
    const float* fs = (const float*)d_in[1];
    float* out  = (float*)d_out;
    float* Pout = out + 1;
    float* Mout = out + 1 + NN;

    cudaFuncSetAttribute(k_gemm_mma, cudaFuncAttributeMaxDynamicSharedMemorySize, GEMM_SMEM);
    cudaFuncSetAttribute(k_sinkall,  cudaFuncAttributeMaxDynamicSharedMemorySize, 81920);

    k_init<<<16, 256>>>();
    k_rownorms<<<2 * N, 256>>>(ft, fs);
    k_convert<<<2 * N, 256>>>(ft, fs);
    k_gemm_mma<<<dim3(32, 32), 256, GEMM_SMEM>>>(Mout);
    k_stats2<<<1, 1>>>();
    k_makeP0<<<N, 256>>>(Mout);
    k_sinkall<<<NB, 256, 81920>>>();
    k_sinv<<<16, 256>>>();
    k_final<<<N, 256>>>(Pout);
    k_loss<<<1, 1>>>(out);
}